// round 3
// baseline (speedup 1.0000x reference)
#include <cuda_runtime.h>

// DeepUDI: per-node relational GAT + GRU.
// N=2048 nodes, R=2 relations, K=32 neighbors, D_IN=F=64, D2=128.
// One 256-thread CTA per node; each 128-thread half handles one relation.
// Key algebraic optimization: scores[k] = Hn[k,:] . (kw @ Jq)  (avoids the
// 32x64x128 HK GEMM). Kernel is HBM-bound: ~740MB of per-node weights
// streamed exactly once; all streaming loads are coalesced.

#define NN   2048
#define RR   2
#define KK   32
#define DD   64
#define FF   64
#define DD2  128
#define HPAD 68   // padded row stride for hn/Hn smem (conflict-free GEMM reads)

__global__ __launch_bounds__(256, 4)
void deepudi_kernel(const void* __restrict__ x_raw,
                    const void* __restrict__ nb_raw,
                    const float* __restrict__ embed,
                    const float* __restrict__ w,
                    const float* __restrict__ qw,
                    const float* __restrict__ kw,
                    const float* __restrict__ Wx,
                    const float* __restrict__ Wn,
                    const float* __restrict__ bx,
                    const float* __restrict__ bn,
                    float* __restrict__ out)
{
    __shared__ float hn_s[RR][KK][HPAD];  // raw neighbor states, later reused as Hn
    __shared__ float h_s[DD];
    __shared__ float J_s[RR][FF];
    __shared__ float Jq_s[RR][DD2];
    __shared__ float v_s[RR][FF];
    __shared__ float sc_s[RR][KK];        // scores, then softmax E
    __shared__ float df_s[RR][FF];
    __shared__ float rdf_s[RR][FF];
    __shared__ float part_s[RR][5][FF];   // matvec cross-half partials
    __shared__ float gru_s[RR][FF];
    __shared__ int   nb_sh[RR][KK];
    __shared__ int   flags[2];            // [0]=idx64 flag, [1]=x[n]

    const int n   = blockIdx.x;
    const int tid = threadIdx.x;
    const int r   = tid >> 7;             // relation handled by this half
    const int wg  = tid & 127;            // thread id within half

    // ---- dtype detection + x[n] ----------------------------------------
    // x = arange(N). If int64, its int32 view is [0,0,1,0,2,0,...] so
    // word[1]==0; if int32 the view is [0,1,2,...] so word[1]==1.
    if (tid == 0) {
        const int* xi = (const int*)x_raw;
        int idx64 = (xi[1] == 0) ? 1 : 0;
        flags[0] = idx64;
        long long xn;
        if (idx64) xn = ((const long long*)x_raw)[n];
        else       xn = (long long)xi[n];
        flags[1] = (int)xn;
    }
    __syncthreads();
    const int idx64 = flags[0];
    const int xn    = flags[1];

    // ---- load neighbor indices + center state --------------------------
    if (wg < KK) {
        long long base = ((long long)n * RR + r) * KK + wg;
        int nbi;
        if (idx64) nbi = (int)((const long long*)nb_raw)[base];
        else       nbi = ((const int*)nb_raw)[base];
        nb_sh[r][wg] = nbi;
    }
    if (tid < DD) h_s[tid] = embed[(long long)xn * DD + tid];
    __syncthreads();

    // ---- gather hn: 32 rows x 64 floats per relation (L2-resident) -----
    #pragma unroll
    for (int j = 0; j < 4; j++) {
        int i  = wg + 128 * j;            // 0..511 float4 slots
        int k  = i >> 4;
        int dv = i & 15;
        int nbi = nb_sh[r][k];
        float4 val = *(const float4*)(embed + (long long)nbi * DD + dv * 4);
        *(float4*)(&hn_s[r][k][dv * 4]) = val;
    }
    __syncthreads();

    const long long nr = (long long)n * RR + r;
    const float* wr = w + nr * (DD * FF);

    // ---- phase 1: Hn = hn @ w  (thread = (k, f-quarter), 16 accs) ------
    const int k  = wg >> 2;
    const int g  = wg & 3;
    const int f0 = g * 16;

    float acc[16];
    #pragma unroll
    for (int j = 0; j < 16; j++) acc[j] = 0.f;

    #pragma unroll 4
    for (int d = 0; d < DD; d++) {
        float a = hn_s[r][k][d];
        const float4* wrow = (const float4*)(wr + d * FF + f0);
        #pragma unroll
        for (int jv = 0; jv < 4; jv++) {
            float4 wv = __ldg(&wrow[jv]);
            acc[jv*4+0] += a * wv.x;
            acc[jv*4+1] += a * wv.y;
            acc[jv*4+2] += a * wv.z;
            acc[jv*4+3] += a * wv.w;
        }
    }
    // J = h @ w (w is L1-hot now)
    if (wg < FF) {
        float j_acc = 0.f;
        #pragma unroll 8
        for (int d = 0; d < DD; d++)
            j_acc += h_s[d] * __ldg(wr + d * FF + wg);
        J_s[r][wg] = j_acc;
    }
    __syncthreads();   // hn fully consumed; J_s published

    // store Hn over the hn buffer (needed later for df)
    #pragma unroll
    for (int jv = 0; jv < 4; jv++) {
        float4 v4 = make_float4(acc[jv*4], acc[jv*4+1], acc[jv*4+2], acc[jv*4+3]);
        *(float4*)(&hn_s[r][k][f0 + jv*4]) = v4;
    }

    // ---- phase 2: Jq[e] = sum_f J[f]*qw[f,e]  (thread = e, coalesced) --
    {
        const float* qwr = qw + nr * (FF * DD2);
        float a2 = 0.f;
        #pragma unroll 8
        for (int f = 0; f < FF; f++)
            a2 += J_s[r][f] * __ldg(qwr + f * DD2 + wg);
        Jq_s[r][wg] = a2;
    }
    __syncthreads();

    // ---- phase 3: v[f] = sum_e kw[f,e]*Jq[e]  (warp-parallel rows) -----
    {
        const float* kwr = kw + nr * (FF * DD2);
        int warp = wg >> 5;
        int lane = wg & 31;
        #pragma unroll 4
        for (int i = 0; i < 16; i++) {
            int f = warp * 16 + i;
            float p = 0.f;
            #pragma unroll
            for (int j = 0; j < 4; j++) {
                int e = lane + 32 * j;
                p += __ldg(kwr + f * DD2 + e) * Jq_s[r][e];
            }
            #pragma unroll
            for (int off = 16; off > 0; off >>= 1)
                p += __shfl_xor_sync(0xffffffffu, p, off);
            if (lane == 0) v_s[r][f] = p;
        }
    }
    __syncthreads();

    // ---- phase 4: scores[k] = Hn[k,:].v  (from live regs + 4-lane red) -
    {
        float s = 0.f;
        #pragma unroll
        for (int j = 0; j < 16; j++) s += acc[j] * v_s[r][f0 + j];
        s += __shfl_xor_sync(0xffffffffu, s, 1);
        s += __shfl_xor_sync(0xffffffffu, s, 2);
        if (g == 0) sc_s[r][k] = s;
    }
    __syncthreads();

    // ---- phase 5: softmax over K=32 (warp 0 of each half) --------------
    if ((wg >> 5) == 0) {
        int lane = wg & 31;
        float s = sc_s[r][lane];
        float m = s;
        #pragma unroll
        for (int off = 16; off > 0; off >>= 1)
            m = fmaxf(m, __shfl_xor_sync(0xffffffffu, m, off));
        float e = __expf(s - m);
        float sum = e;
        #pragma unroll
        for (int off = 16; off > 0; off >>= 1)
            sum += __shfl_xor_sync(0xffffffffu, sum, off);
        sc_s[r][lane] = e / sum;
    }
    __syncthreads();

    // ---- phase 6: df[f] = sum_k E[k]*Hn[k,f] ---------------------------
    if (wg < FF) {
        float d_acc = 0.f;
        #pragma unroll
        for (int kk = 0; kk < KK; kk++)
            d_acc += sc_s[r][kk] * hn_s[r][kk][wg];
        df_s[r][wg] = d_acc;
    }
    __syncthreads();

    // ---- phase 7: GRU gates (5 fused matvecs, then dependent 6th) ------
    const float* Wxr = Wx + nr * (3 * DD * FF);
    const float* Wnr = Wn + nr * (3 * FF * FF);
    const float* bxr = bx + nr * (3 * FF);
    const float* bnr = bn + nr * (3 * FF);
    const int dh = wg >> 6;   // each half of the 128 threads takes 32 d's
    const int f  = wg & 63;

    float a5[5] = {0.f, 0.f, 0.f, 0.f, 0.f};
    #pragma unroll 4
    for (int dd = 0; dd < 32; dd++) {
        int d = dh * 32 + dd;
        float hd  = h_s[d];
        float dfd = df_s[r][d];
        a5[0] += hd  * __ldg(Wxr + (0*DD + d)*FF + f);
        a5[1] += hd  * __ldg(Wxr + (1*DD + d)*FF + f);
        a5[2] += hd  * __ldg(Wxr + (2*DD + d)*FF + f);
        a5[3] += dfd * __ldg(Wnr + (0*FF + d)*FF + f);
        a5[4] += dfd * __ldg(Wnr + (1*FF + d)*FF + f);
    }
    if (dh == 1) {
        #pragma unroll
        for (int j = 0; j < 5; j++) part_s[r][j][f] = a5[j];
    }
    __syncthreads();

    float xh_v = 0.f, z_v = 0.f, df_f = 0.f;
    if (dh == 0) {
        float xr = a5[0] + part_s[r][0][f] + __ldg(bxr + 0*FF + f);
        float xz = a5[1] + part_s[r][1][f] + __ldg(bxr + 1*FF + f);
        xh_v     = a5[2] + part_s[r][2][f] + __ldg(bxr + 2*FF + f);
        float a0 = a5[3] + part_s[r][3][f];
        float a1 = a5[4] + part_s[r][4][f];
        float rg = 1.f / (1.f + __expf(-(xr + a0 + __ldg(bnr + 0*FF + f))));
        z_v      = 1.f / (1.f + __expf(-(xz + a1 + __ldg(bnr + 1*FF + f))));
        df_f = df_s[r][f];
        rdf_s[r][f] = rg * df_f;
    }
    __syncthreads();

    // a2 = (Rg*df) @ Wn[2]
    float a2 = 0.f;
    #pragma unroll 4
    for (int dd = 0; dd < 32; dd++) {
        int d = dh * 32 + dd;
        a2 += rdf_s[r][d] * __ldg(Wnr + (2*FF + d)*FF + f);
    }
    if (dh == 1) part_s[r][0][f] = a2;
    __syncthreads();

    if (dh == 0) {
        float hc = tanhf(xh_v + a2 + part_s[r][0][f] + __ldg(bnr + 2*FF + f));
        gru_s[r][f] = z_v * df_f + (1.f - z_v) * hc;
    }
    __syncthreads();

    // ---- final: out = tanh(mean_r gru) ---------------------------------
    if (tid < FF)
        out[(long long)n * FF + tid] =
            tanhf(0.5f * (gru_s[0][tid] + gru_s[1][tid]));
}

extern "C" void kernel_launch(void* const* d_in, const int* in_sizes, int n_in,
                              void* d_out, int out_size) {
    (void)in_sizes; (void)n_in; (void)out_size;
    deepudi_kernel<<<NN, 256>>>(
        d_in[0],                       // x       (int64 or int32, detected)
        d_in[1],                       // neighbors
        (const float*)d_in[2],         // embed
        (const float*)d_in[3],         // w
        (const float*)d_in[4],         // qw
        (const float*)d_in[5],         // kw
        (const float*)d_in[6],         // Wx
        (const float*)d_in[7],         // Wn
        (const float*)d_in[8],         // bx
        (const float*)d_in[9],         // bn
        (float*)d_out);
}

// round 5
// speedup vs baseline: 1.1986x; 1.1986x over previous
#include <cuda_runtime.h>

// DeepUDI split into two streaming kernels:
//   K1 (attention): per-(n,r) CTA, streams w/qw/kw, writes df to scratch.
//   K2 (GRU):       per-node CTA, streams Wx/Wn, reads df, writes out.
// All bulk gmem reads are float4-coalesced; phases minimized per kernel so
// barrier drains don't starve the memory system.

#define NN   2048
#define RR   2
#define KK   32
#define DD   64
#define FF   64
#define DD2  128
#define HPAD 68

__device__ float df_g[NN * RR * FF];   // 1MB scratch (static, allowed)

__device__ __forceinline__ float sigm(float v) {
    return 1.f / (1.f + __expf(-v));
}

// ===================== Kernel 1: attention -> df ========================
__global__ __launch_bounds__(256)
void attn_kernel(const void* __restrict__ x_raw,
                 const void* __restrict__ nb_raw,
                 const float* __restrict__ embed,
                 const float* __restrict__ w,
                 const float* __restrict__ qw,
                 const float* __restrict__ kw)
{
    __shared__ __align__(16) float hn_s[KK][HPAD];   // hn, then Hn
    __shared__ __align__(16) float w_s[DD * FF];     // staged w (16KB)
    __shared__ float h_s[DD];
    __shared__ float J_s[FF];
    __shared__ __align__(16) float jqp[2][DD2];
    __shared__ float v_s[FF];
    __shared__ float sc_s[KK];
    __shared__ int   nb_sh[KK];
    __shared__ int   flags[2];

    const int nr  = blockIdx.x;        // n*RR + r
    const int n   = nr >> 1;
    const int tid = threadIdx.x;

    // ---- index dtype detection (x = arange; int64 view has word[1]==0) --
    if (tid == 0) {
        const int* xi = (const int*)x_raw;
        int idx64 = (xi[1] == 0) ? 1 : 0;
        flags[0] = idx64;
        flags[1] = idx64 ? (int)((const long long*)x_raw)[n]
                         : xi[n];
    }
    __syncthreads();
    const int idx64 = flags[0];
    const int xn    = flags[1];

    if (tid < KK) {
        long long base = (long long)nr * KK + tid;
        nb_sh[tid] = idx64 ? (int)((const long long*)nb_raw)[base]
                           : ((const int*)nb_raw)[base];
    }
    if (tid >= 64 && tid < 128)
        h_s[tid - 64] = embed[(long long)xn * DD + (tid - 64)];

    // stage w into smem: 1024 float4, fully coalesced stream
    const float4* wr4 = (const float4*)(w + (long long)nr * (DD * FF));
    #pragma unroll
    for (int j = 0; j < 4; j++) {
        int i = tid + 256 * j;
        ((float4*)w_s)[i] = __ldg(wr4 + i);
    }
    __syncthreads();

    // gather hn (embed rows are L2-resident: 512KB table)
    #pragma unroll
    for (int j = 0; j < 2; j++) {
        int i  = tid + 256 * j;        // 0..511 float4 slots
        int k  = i >> 4;
        int dv = i & 15;
        *(float4*)(&hn_s[k][dv * 4]) =
            *(const float4*)(embed + (long long)nb_sh[k] * DD + dv * 4);
    }
    __syncthreads();

    // ---- Hn = hn @ w : thread = (k, f-octant), 8 accumulators ----------
    const int k  = tid >> 3;
    const int g  = tid & 7;
    const int f0 = g * 8;

    float acc[8];
    #pragma unroll
    for (int j = 0; j < 8; j++) acc[j] = 0.f;

    #pragma unroll 4
    for (int d = 0; d < DD; d++) {
        float a = hn_s[k][d];
        float4 w0 = *(const float4*)&w_s[d * FF + f0];
        float4 w1 = *(const float4*)&w_s[d * FF + f0 + 4];
        acc[0] += a * w0.x; acc[1] += a * w0.y;
        acc[2] += a * w0.z; acc[3] += a * w0.w;
        acc[4] += a * w1.x; acc[5] += a * w1.y;
        acc[6] += a * w1.z; acc[7] += a * w1.w;
    }
    // J = h @ w (smem-resident w)
    if (tid < FF) {
        float ja = 0.f;
        #pragma unroll 8
        for (int d = 0; d < DD; d++)
            ja += h_s[d] * w_s[d * FF + tid];
        J_s[tid] = ja;
    }
    __syncthreads();

    // overwrite hn with Hn (all reads of hn are done)
    *(float4*)&hn_s[k][f0]     = make_float4(acc[0], acc[1], acc[2], acc[3]);
    *(float4*)&hn_s[k][f0 + 4] = make_float4(acc[4], acc[5], acc[6], acc[7]);

    // ---- Jq[e] = sum_f J[f]*qw[f,e] : (e, f-half) partials -------------
    {
        const float* qwr = qw + (long long)nr * (FF * DD2);
        int e  = tid & 127;
        int fh = tid >> 7;
        float a2 = 0.f;
        #pragma unroll 8
        for (int f = fh * 32; f < fh * 32 + 32; f++)
            a2 += J_s[f] * __ldg(qwr + f * DD2 + e);
        jqp[fh][e] = a2;
    }
    __syncthreads();

    // ---- v[f] = sum_e kw[f,e]*Jq[e] : 8 warps x 8 rows, float4 --------
    {
        const float* kwr = kw + (long long)nr * (FF * DD2);
        int warp = tid >> 5, lane = tid & 31;
        float4 q0 = ((const float4*)jqp[0])[lane];
        float4 q1 = ((const float4*)jqp[1])[lane];
        float4 q  = make_float4(q0.x + q1.x, q0.y + q1.y,
                                q0.z + q1.z, q0.w + q1.w);
        #pragma unroll
        for (int i = 0; i < 8; i++) {
            int f = warp * 8 + i;
            float4 kv = __ldg((const float4*)(kwr + f * DD2) + lane);
            float p = kv.x * q.x + kv.y * q.y + kv.z * q.z + kv.w * q.w;
            #pragma unroll
            for (int off = 16; off > 0; off >>= 1)
                p += __shfl_xor_sync(0xffffffffu, p, off);
            if (lane == 0) v_s[f] = p;
        }
    }
    __syncthreads();

    // ---- scores[k] = Hn[k,:].v  (from live accs, reduce over 8 lanes) --
    {
        float s = 0.f;
        #pragma unroll
        for (int j = 0; j < 8; j++) s += acc[j] * v_s[f0 + j];
        s += __shfl_xor_sync(0xffffffffu, s, 1);
        s += __shfl_xor_sync(0xffffffffu, s, 2);
        s += __shfl_xor_sync(0xffffffffu, s, 4);
        if (g == 0) sc_s[k] = s;
    }
    __syncthreads();

    // ---- softmax over K=32 (warp 0) ------------------------------------
    if (tid < 32) {
        float s = sc_s[tid];
        float m = s;
        #pragma unroll
        for (int off = 16; off > 0; off >>= 1)
            m = fmaxf(m, __shfl_xor_sync(0xffffffffu, m, off));
        float e = __expf(s - m);
        float sum = e;
        #pragma unroll
        for (int off = 16; off > 0; off >>= 1)
            sum += __shfl_xor_sync(0xffffffffu, sum, off);
        sc_s[tid] = e / sum;
    }
    __syncthreads();

    // ---- df[f] = sum_k E[k]*Hn[k,f] -> scratch -------------------------
    if (tid < FF) {
        float da = 0.f;
        #pragma unroll
        for (int kk = 0; kk < KK; kk++)
            da += sc_s[kk] * hn_s[kk][tid];
        df_g[(long long)nr * FF + tid] = da;
    }
}

// ===================== Kernel 2: GRU + combine ==========================
__global__ __launch_bounds__(256)
void gru_kernel(const void* __restrict__ x_raw,
                const float* __restrict__ embed,
                const float* __restrict__ Wx,
                const float* __restrict__ Wn,
                const float* __restrict__ bx,
                const float* __restrict__ bn,
                float* __restrict__ out)
{
    __shared__ float h_s[DD];
    __shared__ float df_s[RR][FF];
    __shared__ __align__(16) float part[RR][8][5][FF];   // 20.5KB
    __shared__ __align__(16) float red[RR][6][FF];
    __shared__ float rdf_s[RR][FF];
    __shared__ float gru_s[RR][FF];
    __shared__ int   flags[2];

    const int n   = blockIdx.x;
    const int tid = threadIdx.x;
    const int r   = tid >> 7;
    const int wg  = tid & 127;

    if (tid == 0) {
        const int* xi = (const int*)x_raw;
        int idx64 = (xi[1] == 0) ? 1 : 0;
        flags[0] = idx64;
        flags[1] = idx64 ? (int)((const long long*)x_raw)[n] : xi[n];
    }
    __syncthreads();
    const int xn = flags[1];

    if (tid < DD) h_s[tid] = embed[(long long)xn * DD + tid];
    if (wg < FF)  df_s[r][wg] = df_g[((long long)n * RR + r) * FF + wg];
    __syncthreads();

    const long long nr = (long long)n * RR + r;
    const float* Wxr = Wx + nr * (3 * DD * FF);
    const float* Wnr = Wn + nr * (3 * FF * FF);
    const float* bxr = bx + nr * (3 * FF);
    const float* bnr = bn + nr * (3 * FF);

    const int fg = wg & 15;            // 16 f-groups of 4
    const int ds = wg >> 4;            // 8 d-slices of 8
    const int f4 = fg * 4;

    // ---- 5 fused matvecs: xr,xz,xh (h) + a0,a1 (df), float4 streams ----
    float4 a0 = make_float4(0,0,0,0), a1 = a0, a2v = a0, a3 = a0, a4 = a0;
    #pragma unroll
    for (int dd = 0; dd < 8; dd++) {
        int d = ds * 8 + dd;
        float hd  = h_s[d];
        float dfd = df_s[r][d];
        float4 x0 = __ldg((const float4*)(Wxr + (0*DD + d)*FF + f4));
        float4 x1 = __ldg((const float4*)(Wxr + (1*DD + d)*FF + f4));
        float4 x2 = __ldg((const float4*)(Wxr + (2*DD + d)*FF + f4));
        float4 n0 = __ldg((const float4*)(Wnr + (0*FF + d)*FF + f4));
        float4 n1 = __ldg((const float4*)(Wnr + (1*FF + d)*FF + f4));
        a0.x += hd*x0.x;  a0.y += hd*x0.y;  a0.z += hd*x0.z;  a0.w += hd*x0.w;
        a1.x += hd*x1.x;  a1.y += hd*x1.y;  a1.z += hd*x1.z;  a1.w += hd*x1.w;
        a2v.x+= hd*x2.x;  a2v.y+= hd*x2.y;  a2v.z+= hd*x2.z;  a2v.w+= hd*x2.w;
        a3.x += dfd*n0.x; a3.y += dfd*n0.y; a3.z += dfd*n0.z; a3.w += dfd*n0.w;
        a4.x += dfd*n1.x; a4.y += dfd*n1.y; a4.z += dfd*n1.z; a4.w += dfd*n1.w;
    }
    *(float4*)&part[r][ds][0][f4] = a0;
    *(float4*)&part[r][ds][1][f4] = a1;
    *(float4*)&part[r][ds][2][f4] = a2v;
    *(float4*)&part[r][ds][3][f4] = a3;
    *(float4*)&part[r][ds][4][f4] = a4;
    __syncthreads();

    // reduce over 8 d-slices: 80 float4 sums per relation
    if (wg < 80) {
        int gate = wg >> 4, fgi = wg & 15;
        float4 s = make_float4(0,0,0,0);
        #pragma unroll
        for (int d2 = 0; d2 < 8; d2++) {
            float4 v = *(const float4*)&part[r][d2][gate][fgi * 4];
            s.x += v.x; s.y += v.y; s.z += v.z; s.w += v.w;
        }
        *(float4*)&red[r][gate][fgi * 4] = s;
    }
    __syncthreads();

    // ---- gate math (64 threads per relation) ---------------------------
    float xh_v = 0.f, z_v = 0.f, dff = 0.f;
    if (wg < FF) {
        int f = wg;
        float xr = red[r][0][f] + __ldg(bxr + f);
        float xz = red[r][1][f] + __ldg(bxr + FF + f);
        xh_v     = red[r][2][f] + __ldg(bxr + 2*FF + f);
        float rg = sigm(xr + red[r][3][f] + __ldg(bnr + f));
        z_v      = sigm(xz + red[r][4][f] + __ldg(bnr + FF + f));
        dff = df_s[r][f];
        rdf_s[r][f] = rg * dff;
    }
    __syncthreads();

    // ---- c = (Rg*df) @ Wn[2] -------------------------------------------
    float4 c = make_float4(0,0,0,0);
    #pragma unroll
    for (int dd = 0; dd < 8; dd++) {
        int d = ds * 8 + dd;
        float rd = rdf_s[r][d];
        float4 n2 = __ldg((const float4*)(Wnr + (2*FF + d)*FF + f4));
        c.x += rd*n2.x; c.y += rd*n2.y; c.z += rd*n2.z; c.w += rd*n2.w;
    }
    *(float4*)&part[r][ds][0][f4] = c;
    __syncthreads();

    if (wg < 16) {
        float4 s = make_float4(0,0,0,0);
        #pragma unroll
        for (int d2 = 0; d2 < 8; d2++) {
            float4 v = *(const float4*)&part[r][d2][0][wg * 4];
            s.x += v.x; s.y += v.y; s.z += v.z; s.w += v.w;
        }
        *(float4*)&red[r][5][wg * 4] = s;
    }
    __syncthreads();

    if (wg < FF) {
        float hc = tanhf(xh_v + red[r][5][wg] + __ldg(bnr + 2*FF + wg));
        gru_s[r][wg] = z_v * dff + (1.f - z_v) * hc;
    }
    __syncthreads();

    if (tid < FF)
        out[(long long)n * FF + tid] =
            tanhf(0.5f * (gru_s[0][tid] + gru_s[1][tid]));
}

extern "C" void kernel_launch(void* const* d_in, const int* in_sizes, int n_in,
                              void* d_out, int out_size) {
    (void)in_sizes; (void)n_in; (void)out_size;
    attn_kernel<<<NN * RR, 256>>>(
        d_in[0], d_in[1],
        (const float*)d_in[2],         // embed
        (const float*)d_in[3],         // w
        (const float*)d_in[4],         // qw
        (const float*)d_in[5]);        // kw
    gru_kernel<<<NN, 256>>>(
        d_in[0],
        (const float*)d_in[2],         // embed
        (const float*)d_in[6],         // Wx
        (const float*)d_in[7],         // Wn
        (const float*)d_in[8],         // bx
        (const float*)d_in[9],         // bn
        (float*)d_out);
}